// round 10
// baseline (speedup 1.0000x reference)
#include <cuda_runtime.h>

#define NC 128
#define EPS 1e-5f
#define RAYS_PER_CTA 8          // 8 warps/CTA, one ray per warp
#define THREADS (RAYS_PER_CTA * 32)

__global__ __launch_bounds__(THREADS) void pdf_sampler_kernel(
    const float* __restrict__ deltas,
    const float* __restrict__ density,
    const float* __restrict__ bins,
    const float* __restrict__ u,
    float* __restrict__ out)
{
    const int lane = threadIdx.x & 31;
    const int wrp  = threadIdx.x >> 5;
    const int ray  = blockIdx.x * RAYS_PER_CTA + wrp;

    // Skewed cdf: logical i at phys 20*(i>>4) + (i&15).
    // Gap word 20k+16 duplicates cdf[16(k+1)] so "+1" reads never leave the block.
    __shared__ __align__(16) float cfs_sh[RAYS_PER_CTA][160];
    __shared__ __align__(16) float bins_sh[RAYS_PER_CTA][NC];  // bins[0..127]
    __shared__ __align__(16) float ds_sh[RAYS_PER_CTA][NC];    // deltas[0..127]

    const size_t base_c = (size_t)ray * NC;

    // ---- coalesced loads (full bins row NOT loaded; only near) ----
    const float4 dv = *(const float4*)(deltas  + base_c + 4 * lane);
    const float4 rv = *(const float4*)(density + base_c + 4 * lane);
    const float4 uv = *(const float4*)(u       + base_c + 4 * lane);
    const float nearv = bins[(size_t)ray * (NC + 1)];   // warp-uniform

    // ---- per-lane serial prefixes ----
    const float dd0 = dv.x * rv.x;
    const float dd1 = dv.y * rv.y;
    const float dd2 = dv.z * rv.z;
    const float dd3 = dv.w * rv.w;
    const float pA0 = dd0, pA1 = pA0 + dd1, pA2 = pA1 + dd2, pA3 = pA2 + dd3;
    const float pD0 = dv.x, pD1 = pD0 + dv.y, pD2 = pD1 + dv.z, pD3 = pD2 + dv.w;

    // ---- fused dual warp scan over lane totals ----
    float sA = pA3, sD = pD3;
    #pragma unroll
    for (int o = 1; o < 32; o <<= 1) {
        const float nA = __shfl_up_sync(0xffffffffu, sA, o);
        const float nD = __shfl_up_sync(0xffffffffu, sD, o);
        if (lane >= o) { sA += nA; sD += nD; }
    }
    const float offA = sA - pA3;
    const float offD = sD - pD3;

    // ---- telescoped cdf ----
    const float total = __shfl_sync(0xffffffffu, sA, 31);
    const float wsum  = 1.0f - __expf(-total);
    const float pad   = fmaxf(EPS - wsum, 0.0f);
    const float inv   = __fdividef(1.0f, wsum + pad);
    const float ps    = pad * (1.0f / (float)NC);

    const int e = 4 * lane;
    float4 cv;
    cv.x = fminf(1.0f, (1.0f - __expf(-(offA + pA0)) + ps * (float)(e + 1)) * inv);
    cv.y = fminf(1.0f, (1.0f - __expf(-(offA + pA1)) + ps * (float)(e + 2)) * inv);
    cv.z = fminf(1.0f, (1.0f - __expf(-(offA + pA2)) + ps * (float)(e + 3)) * inv);
    cv.w = fminf(1.0f, (1.0f - __expf(-(offA + pA3)) + ps * (float)(e + 4)) * inv);

    const float cprev_raw = __shfl_up_sync(0xffffffffu, cv.w, 1);
    const float cprev = (lane == 0) ? 0.0f : cprev_raw;   // cdf[e]

    // ---- store skewed cdf quad (aligned STS.128) + boundary duplicates ----
    const int blk   = e >> 4;
    const int pbase = blk * 20 + (e & 15);
    *(float4*)(&cfs_sh[wrp][pbase]) = make_float4(cprev, cv.x, cv.y, cv.z);
    if ((e & 15) == 0 && e > 0)
        cfs_sh[wrp][blk * 20 - 4] = cprev;          // cdf[16k] into gap of block k-1
    if (lane == 31)
        cfs_sh[wrp][156] = cv.w;                    // cdf[128] into gap of block 7

    const float be0 = nearv + offD;
    *(float4*)(&bins_sh[wrp][e]) = make_float4(be0, be0 + pD0, be0 + pD1, be0 + pD2);
    *(float4*)(&ds_sh[wrp][e]) = dv;

    __syncwarp();

    const float* __restrict__ cf = cfs_sh[wrp];
    const float* __restrict__ bn = bins_sh[wrp];
    const float* __restrict__ ds = ds_sh[wrp];

    // hoisted coarse probes (broadcast LDS; logical 16..112 at phys 20k)
    const float g16  = cf[20],  g32 = cf[40],  g48  = cf[60],  g64 = cf[80];
    const float g80  = cf[100], g96 = cf[120], g112 = cf[140];

    float uu[4] = { uv.x, uv.y, uv.z, uv.w };
    int   m[4];          // coarse block index 0..7
    int   pb[4];         // phys position: 20*m + off

    #pragma unroll
    for (int s = 0; s < 4; s++) {
        const bool l1 = (g64 <= uu[s]);
        const bool l2 = ((l1 ? g96 : g32) <= uu[s]);
        const float v3 = l1 ? (l2 ? g112 : g80) : (l2 ? g48 : g16);
        const bool l3 = (v3 <= uu[s]);
        m[s]  = (l1 ? 4 : 0) + (l2 ? 2 : 0) + (l3 ? 1 : 0);
        pb[s] = m[s] * 20;
    }

    // in-block levels: probes never cross the 16-block (8+4+2+1 = 15)
    #pragma unroll
    for (int step = 8; step >= 1; step >>= 1) {
        float pv[4];
        #pragma unroll
        for (int s = 0; s < 4; s++) pv[s] = cf[pb[s] + step];
        #pragma unroll
        for (int s = 0; s < 4; s++) if (pv[s] <= uu[s]) pb[s] += step;
    }

    // gathers: c1 at pb+1 valid via gap duplicates; logical pos = pb - 4*m
    float c0[4], c1[4], b0[4], db[4];
    int pos[4];
    #pragma unroll
    for (int s = 0; s < 4; s++) c0[s] = cf[pb[s]];
    #pragma unroll
    for (int s = 0; s < 4; s++) c1[s] = cf[pb[s] + 1];
    #pragma unroll
    for (int s = 0; s < 4; s++) pos[s] = pb[s] - 4 * m[s];
    #pragma unroll
    for (int s = 0; s < 4; s++) b0[s] = bn[pos[s]];
    #pragma unroll
    for (int s = 0; s < 4; s++) db[s] = ds[pos[s]];

    float r[4];
    #pragma unroll
    for (int s = 0; s < 4; s++) {
        float den = c1[s] - c0[s];
        den = (den < EPS) ? 1.0f : den;
        r[s] = fmaf(__fdividef(uu[s] - c0[s], den), db[s], b0[s]);
    }

    *(float4*)(out + base_c + 4 * lane) = make_float4(r[0], r[1], r[2], r[3]);
}

extern "C" void kernel_launch(void* const* d_in, const int* in_sizes, int n_in,
                              void* d_out, int out_size) {
    const float* deltas  = (const float*)d_in[0];
    const float* density = (const float*)d_in[1];
    const float* bins    = (const float*)d_in[2];
    const float* u       = (const float*)d_in[3];
    float* out = (float*)d_out;

    int R = in_sizes[0] / NC;               // 131072
    pdf_sampler_kernel<<<R / RAYS_PER_CTA, THREADS>>>(deltas, density, bins, u, out);
}

// round 11
// speedup vs baseline: 1.0265x; 1.0265x over previous
#include <cuda_runtime.h>

#define NC 128
#define EPS 1e-5f
#define RAYS_PER_CTA 8          // 8 warps/CTA, one ray per warp
#define THREADS (RAYS_PER_CTA * 32)

__global__ __launch_bounds__(THREADS) void pdf_sampler_kernel(
    const float* __restrict__ deltas,
    const float* __restrict__ density,
    const float* __restrict__ bins,
    const float* __restrict__ u,
    float* __restrict__ out)
{
    const int lane = threadIdx.x & 31;
    const int wrp  = threadIdx.x >> 5;
    const int ray  = blockIdx.x * RAYS_PER_CTA + wrp;

    // All three tables share the stride-20 padded layout:
    //   logical i  ->  phys 20*(i>>4) + (i&15)
    // cf gap slot 20k+16 duplicates cdf[16(k+1)] so cf[pb+1] is always valid.
    __shared__ __align__(16) float cf_sh[RAYS_PER_CTA][160];  // cdf[0..128]
    __shared__ __align__(16) float bn_sh[RAYS_PER_CTA][160];  // bins[0..127]
    __shared__ __align__(16) float sl_sh[RAYS_PER_CTA][160];  // slope[0..127]

    const size_t base_c = (size_t)ray * NC;

    // ---- coalesced loads (full bins row NOT loaded; only near) ----
    const float4 dv = *(const float4*)(deltas  + base_c + 4 * lane);
    const float4 rv = *(const float4*)(density + base_c + 4 * lane);
    const float4 uv = *(const float4*)(u       + base_c + 4 * lane);
    const float nearv = bins[(size_t)ray * (NC + 1)];   // warp-uniform

    // ---- per-lane serial prefixes ----
    const float dd0 = dv.x * rv.x;
    const float dd1 = dv.y * rv.y;
    const float dd2 = dv.z * rv.z;
    const float dd3 = dv.w * rv.w;
    const float pA0 = dd0, pA1 = pA0 + dd1, pA2 = pA1 + dd2, pA3 = pA2 + dd3;
    const float pD0 = dv.x, pD1 = pD0 + dv.y, pD2 = pD1 + dv.z, pD3 = pD2 + dv.w;

    // ---- fused dual warp scan over lane totals ----
    float sA = pA3, sD = pD3;
    #pragma unroll
    for (int o = 1; o < 32; o <<= 1) {
        const float nA = __shfl_up_sync(0xffffffffu, sA, o);
        const float nD = __shfl_up_sync(0xffffffffu, sD, o);
        if (lane >= o) { sA += nA; sD += nD; }
    }
    const float offA = sA - pA3;
    const float offD = sD - pD3;

    // ---- telescoped cdf: cumsum(w)[i] = 1 - exp(-cumsum(dd)[i]) ----
    const float total = __shfl_sync(0xffffffffu, sA, 31);
    const float wsum  = 1.0f - __expf(-total);
    const float pad   = fmaxf(EPS - wsum, 0.0f);
    const float inv   = __fdividef(1.0f, wsum + pad);
    const float ps    = pad * (1.0f / (float)NC);

    const int e = 4 * lane;
    float4 cv;
    cv.x = fminf(1.0f, (1.0f - __expf(-(offA + pA0)) + ps * (float)(e + 1)) * inv);
    cv.y = fminf(1.0f, (1.0f - __expf(-(offA + pA1)) + ps * (float)(e + 2)) * inv);
    cv.z = fminf(1.0f, (1.0f - __expf(-(offA + pA2)) + ps * (float)(e + 3)) * inv);
    cv.w = fminf(1.0f, (1.0f - __expf(-(offA + pA3)) + ps * (float)(e + 4)) * inv);

    const float cprev_raw = __shfl_up_sync(0xffffffffu, cv.w, 1);
    const float cprev = (lane == 0) ? 0.0f : cprev_raw;   // cdf[e]

    // ---- per-element slopes: slope = delta / clamp(cdf[k+1]-cdf[k]) ----
    float den0 = cv.x - cprev; den0 = (den0 < EPS) ? 1.0f : den0;
    float den1 = cv.y - cv.x;  den1 = (den1 < EPS) ? 1.0f : den1;
    float den2 = cv.z - cv.y;  den2 = (den2 < EPS) ? 1.0f : den2;
    float den3 = cv.w - cv.z;  den3 = (den3 < EPS) ? 1.0f : den3;
    const float sl0 = __fdividef(dv.x, den0);
    const float sl1 = __fdividef(dv.y, den1);
    const float sl2 = __fdividef(dv.z, den2);
    const float sl3 = __fdividef(dv.w, den3);

    // ---- build padded shared tables (aligned STS.128; phys quad in-block) ----
    const int pb0 = e + (e >> 4) * 4;     // 20*(e>>4) + (e&15)
    *(float4*)(&cf_sh[wrp][pb0]) = make_float4(cprev, cv.x, cv.y, cv.z);
    const float be0 = nearv + offD;
    *(float4*)(&bn_sh[wrp][pb0]) = make_float4(be0, be0 + pD0, be0 + pD1, be0 + pD2);
    *(float4*)(&sl_sh[wrp][pb0]) = make_float4(sl0, sl1, sl2, sl3);
    if ((e & 15) == 0 && e > 0)
        cf_sh[wrp][(e >> 4) * 20 - 4] = cprev;   // dup cdf[16k] into gap of block k-1
    if (lane == 31)
        cf_sh[wrp][156] = cv.w;                  // dup cdf[128] into gap of block 7

    __syncwarp();

    const float* __restrict__ cf = cf_sh[wrp];
    const float* __restrict__ bn = bn_sh[wrp];
    const float* __restrict__ sl = sl_sh[wrp];

    // hoisted coarse probes (warp-uniform broadcasts; logical 32/64/96 -> phys 40/80/120)
    const float g64 = cf[80];
    const float g32 = cf[40];
    const float g96 = cf[120];

    float uu[4] = { uv.x, uv.y, uv.z, uv.w };
    int pb[4];

    #pragma unroll
    for (int s = 0; s < 4; s++) {
        const bool l1 = (g64 <= uu[s]);
        pb[s] = l1 ? 80 : 0;
        const float v2 = l1 ? g96 : g32;
        if (v2 <= uu[s]) pb[s] += 40;
    }
    // level 16 (phys step 20), then in-block 8/4/2/1 — all constant steps
    #pragma unroll
    for (int s = 0; s < 4; s++) if (cf[pb[s] + 20] <= uu[s]) pb[s] += 20;
    #pragma unroll
    for (int step = 8; step >= 1; step >>= 1) {
        float pv[4];
        #pragma unroll
        for (int s = 0; s < 4; s++) pv[s] = cf[pb[s] + step];
        #pragma unroll
        for (int s = 0; s < 4; s++) if (pv[s] <= uu[s]) pb[s] += step;
    }

    // ---- gathers (3 per sample) + 2-op interpolation ----
    float c0[4], b0[4], ss[4];
    #pragma unroll
    for (int s = 0; s < 4; s++) c0[s] = cf[pb[s]];
    #pragma unroll
    for (int s = 0; s < 4; s++) b0[s] = bn[pb[s]];
    #pragma unroll
    for (int s = 0; s < 4; s++) ss[s] = sl[pb[s]];

    float r[4];
    #pragma unroll
    for (int s = 0; s < 4; s++)
        r[s] = fmaf(ss[s], uu[s] - c0[s], b0[s]);

    *(float4*)(out + base_c + 4 * lane) = make_float4(r[0], r[1], r[2], r[3]);
}

extern "C" void kernel_launch(void* const* d_in, const int* in_sizes, int n_in,
                              void* d_out, int out_size) {
    const float* deltas  = (const float*)d_in[0];
    const float* density = (const float*)d_in[1];
    const float* bins    = (const float*)d_in[2];
    const float* u       = (const float*)d_in[3];
    float* out = (float*)d_out;

    int R = in_sizes[0] / NC;               // 131072
    pdf_sampler_kernel<<<R / RAYS_PER_CTA, THREADS>>>(deltas, density, bins, u, out);
}

// round 12
// speedup vs baseline: 1.0739x; 1.0462x over previous
#include <cuda_runtime.h>

#define NC 128
#define EPS 1e-5f
#define RAYS_PER_CTA 8          // 8 warps/CTA, one ray per warp
#define THREADS (RAYS_PER_CTA * 32)

__global__ __launch_bounds__(THREADS) void pdf_sampler_kernel(
    const float* __restrict__ deltas,
    const float* __restrict__ density,
    const float* __restrict__ bins,
    const float* __restrict__ u,
    float* __restrict__ out)
{
    const int lane = threadIdx.x & 31;
    const int wrp  = threadIdx.x >> 5;
    const int ray  = blockIdx.x * RAYS_PER_CTA + wrp;

    // cdf_full[p] = cdf[p], p = 0..128 (probe table; row padded to 132)
    __shared__ __align__(16) float  cf_sh[RAYS_PER_CTA][132];
    // fit[p] = (slope, intercept):  sample = fma(slope, u, intercept)
    __shared__ __align__(16) float2 fit_sh[RAYS_PER_CTA][NC];

    const size_t base_c = (size_t)ray * NC;

    // ---- coalesced loads (full bins row NOT loaded; only near) ----
    const float4 dv = *(const float4*)(deltas  + base_c + 4 * lane);
    const float4 rv = *(const float4*)(density + base_c + 4 * lane);
    const float4 uv = *(const float4*)(u       + base_c + 4 * lane);
    const float nearv = bins[(size_t)ray * (NC + 1)];   // warp-uniform

    // ---- per-lane serial prefixes ----
    const float dd0 = dv.x * rv.x;
    const float dd1 = dv.y * rv.y;
    const float dd2 = dv.z * rv.z;
    const float dd3 = dv.w * rv.w;
    const float pA0 = dd0, pA1 = pA0 + dd1, pA2 = pA1 + dd2, pA3 = pA2 + dd3;
    const float pD0 = dv.x, pD1 = pD0 + dv.y, pD2 = pD1 + dv.z, pD3 = pD2 + dv.w;

    // ---- fused dual warp scan over lane totals ----
    float sA = pA3, sD = pD3;
    #pragma unroll
    for (int o = 1; o < 32; o <<= 1) {
        const float nA = __shfl_up_sync(0xffffffffu, sA, o);
        const float nD = __shfl_up_sync(0xffffffffu, sD, o);
        if (lane >= o) { sA += nA; sD += nD; }
    }
    const float offA = sA - pA3;
    const float offD = sD - pD3;

    // ---- telescoped cdf: cumsum(w)[i] = 1 - exp(-cumsum(dd)[i]) ----
    const float total = __shfl_sync(0xffffffffu, sA, 31);
    const float wsum  = 1.0f - __expf(-total);
    const float pad   = fmaxf(EPS - wsum, 0.0f);
    const float inv   = __fdividef(1.0f, wsum + pad);
    const float ps    = pad * (1.0f / (float)NC);

    const int e = 4 * lane;
    float4 cv;
    cv.x = fminf(1.0f, (1.0f - __expf(-(offA + pA0)) + ps * (float)(e + 1)) * inv);
    cv.y = fminf(1.0f, (1.0f - __expf(-(offA + pA1)) + ps * (float)(e + 2)) * inv);
    cv.z = fminf(1.0f, (1.0f - __expf(-(offA + pA2)) + ps * (float)(e + 3)) * inv);
    cv.w = fminf(1.0f, (1.0f - __expf(-(offA + pA3)) + ps * (float)(e + 4)) * inv);

    const float cprev_raw = __shfl_up_sync(0xffffffffu, cv.w, 1);
    const float cprev = (lane == 0) ? 0.0f : cprev_raw;   // cdf[e]

    // ---- probe table store (1 aligned STS.128 + tail dup) ----
    *(float4*)(&cf_sh[wrp][e]) = make_float4(cprev, cv.x, cv.y, cv.z);
    if (lane == 31) cf_sh[wrp][NC] = cv.w;       // cdf[128]

    // ---- linear-fit table: slope = delta/clamp(den), intercept = b0 - slope*c0 ----
    const float be0 = nearv + offD;              // bins[e]
    float den0 = cv.x - cprev; den0 = (den0 < EPS) ? 1.0f : den0;
    float den1 = cv.y - cv.x;  den1 = (den1 < EPS) ? 1.0f : den1;
    float den2 = cv.z - cv.y;  den2 = (den2 < EPS) ? 1.0f : den2;
    float den3 = cv.w - cv.z;  den3 = (den3 < EPS) ? 1.0f : den3;
    const float s0 = __fdividef(dv.x, den0);
    const float s1 = __fdividef(dv.y, den1);
    const float s2 = __fdividef(dv.z, den2);
    const float s3 = __fdividef(dv.w, den3);
    const float i0 = fmaf(-s0, cprev, be0);
    const float i1 = fmaf(-s1, cv.x, be0 + pD0);
    const float i2 = fmaf(-s2, cv.y, be0 + pD1);
    const float i3 = fmaf(-s3, cv.z, be0 + pD2);
    // two aligned STS.128
    *(float4*)(&fit_sh[wrp][e])     = make_float4(s0, i0, s1, i1);
    *(float4*)(&fit_sh[wrp][e + 2]) = make_float4(s2, i2, s3, i3);

    __syncwarp();

    const float*  __restrict__ cf = cf_sh[wrp];
    const float2* __restrict__ ft = fit_sh[wrp];

    // hoisted level-1/2 probe values (broadcast loads)
    const float g64 = cf[64];
    const float g32 = cf[32];
    const float g96 = cf[96];

    // ---- 4 interleaved binary searches (R9 structure) ----
    float uu[4] = { uv.x, uv.y, uv.z, uv.w };
    int pos[4];

    #pragma unroll
    for (int s = 0; s < 4; s++) {
        const bool l1 = (g64 <= uu[s]);
        pos[s] = l1 ? 64 : 0;
        const float v2 = l1 ? g96 : g32;
        if (v2 <= uu[s]) pos[s] += 32;
    }
    #pragma unroll
    for (int step = 16; step >= 1; step >>= 1) {
        float pv[4];
        #pragma unroll
        for (int s = 0; s < 4; s++) pv[s] = cf[pos[s] + step];
        #pragma unroll
        for (int s = 0; s < 4; s++) if (pv[s] <= uu[s]) pos[s] += step;
    }

    // ---- single LDS.64 gather per sample + FMA ----
    float2 f[4];
    #pragma unroll
    for (int s = 0; s < 4; s++) f[s] = ft[pos[s]];

    float r[4];
    #pragma unroll
    for (int s = 0; s < 4; s++)
        r[s] = fmaf(f[s].x, uu[s], f[s].y);

    *(float4*)(out + base_c + 4 * lane) = make_float4(r[0], r[1], r[2], r[3]);
}

extern "C" void kernel_launch(void* const* d_in, const int* in_sizes, int n_in,
                              void* d_out, int out_size) {
    const float* deltas  = (const float*)d_in[0];
    const float* density = (const float*)d_in[1];
    const float* bins    = (const float*)d_in[2];
    const float* u       = (const float*)d_in[3];
    float* out = (float*)d_out;

    int R = in_sizes[0] / NC;               // 131072
    pdf_sampler_kernel<<<R / RAYS_PER_CTA, THREADS>>>(deltas, density, bins, u, out);
}

// round 13
// speedup vs baseline: 1.0786x; 1.0043x over previous
#include <cuda_runtime.h>

#define NC 128
#define EPS 1e-5f
#define RAYS_PER_CTA 8          // 8 warps/CTA, one ray per warp
#define THREADS (RAYS_PER_CTA * 32)
#define FULL 0xffffffffu

__global__ __launch_bounds__(THREADS) void pdf_sampler_kernel(
    const float* __restrict__ deltas,
    const float* __restrict__ density,
    const float* __restrict__ bins,
    const float* __restrict__ u,
    float* __restrict__ out)
{
    const int lane = threadIdx.x & 31;
    const int wrp  = threadIdx.x >> 5;
    const int ray  = blockIdx.x * RAYS_PER_CTA + wrp;

    // Only table left in shared: fit[p] = (slope, intercept); s = fma(slope,u,intercept)
    __shared__ __align__(16) float2 fit_sh[RAYS_PER_CTA][NC];

    const size_t base_c = (size_t)ray * NC;

    // ---- coalesced loads ----
    const float4 dv = *(const float4*)(deltas  + base_c + 4 * lane);
    const float4 rv = *(const float4*)(density + base_c + 4 * lane);
    const float4 uv = *(const float4*)(u       + base_c + 4 * lane);
    const float nearv = bins[(size_t)ray * (NC + 1)];   // warp-uniform

    // ---- per-lane serial prefixes ----
    const float dd0 = dv.x * rv.x;
    const float dd1 = dv.y * rv.y;
    const float dd2 = dv.z * rv.z;
    const float dd3 = dv.w * rv.w;
    const float pA0 = dd0, pA1 = pA0 + dd1, pA2 = pA1 + dd2, pA3 = pA2 + dd3;
    const float pD0 = dv.x, pD1 = pD0 + dv.y, pD2 = pD1 + dv.z, pD3 = pD2 + dv.w;

    // ---- fused dual warp scan over lane totals ----
    float sA = pA3, sD = pD3;
    #pragma unroll
    for (int o = 1; o < 32; o <<= 1) {
        const float nA = __shfl_up_sync(FULL, sA, o);
        const float nD = __shfl_up_sync(FULL, sD, o);
        if (lane >= o) { sA += nA; sD += nD; }
    }
    const float offA = sA - pA3;
    const float offD = sD - pD3;

    // ---- telescoped cdf: cumsum(w)[i] = 1 - exp(-cumsum(dd)[i]) ----
    const float total = __shfl_sync(FULL, sA, 31);
    const float wsum  = 1.0f - __expf(-total);
    const float pad   = fmaxf(EPS - wsum, 0.0f);
    const float inv   = __fdividef(1.0f, wsum + pad);
    const float ps    = pad * (1.0f / (float)NC);

    const int e = 4 * lane;
    float4 cv;
    cv.x = fminf(1.0f, (1.0f - __expf(-(offA + pA0)) + ps * (float)(e + 1)) * inv);
    cv.y = fminf(1.0f, (1.0f - __expf(-(offA + pA1)) + ps * (float)(e + 2)) * inv);
    cv.z = fminf(1.0f, (1.0f - __expf(-(offA + pA2)) + ps * (float)(e + 3)) * inv);
    cv.w = fminf(1.0f, (1.0f - __expf(-(offA + pA3)) + ps * (float)(e + 4)) * inv);

    const float cprev_raw = __shfl_up_sync(FULL, cv.w, 1);
    const float cprev = (lane == 0) ? 0.0f : cprev_raw;   // cdf[e] = cdf[4*lane]

    // ---- linear-fit table: slope = delta/clamp(den), intercept = b0 - slope*c0 ----
    const float be0 = nearv + offD;              // bins[e]
    float den0 = cv.x - cprev; den0 = (den0 < EPS) ? 1.0f : den0;
    float den1 = cv.y - cv.x;  den1 = (den1 < EPS) ? 1.0f : den1;
    float den2 = cv.z - cv.y;  den2 = (den2 < EPS) ? 1.0f : den2;
    float den3 = cv.w - cv.z;  den3 = (den3 < EPS) ? 1.0f : den3;
    const float s0 = __fdividef(dv.x, den0);
    const float s1 = __fdividef(dv.y, den1);
    const float s2 = __fdividef(dv.z, den2);
    const float s3 = __fdividef(dv.w, den3);
    const float i0 = fmaf(-s0, cprev, be0);
    const float i1 = fmaf(-s1, cv.x, be0 + pD0);
    const float i2 = fmaf(-s2, cv.y, be0 + pD1);
    const float i3 = fmaf(-s3, cv.z, be0 + pD2);
    *(float4*)(&fit_sh[wrp][e])     = make_float4(s0, i0, s1, i1);
    *(float4*)(&fit_sh[wrp][e + 2]) = make_float4(s2, i2, s3, i3);

    __syncwarp();

    const float2* __restrict__ ft = fit_sh[wrp];

    // coarse probe values from registers (cdf[32/64/96] = cprev of lanes 8/16/24)
    const float g32 = __shfl_sync(FULL, cprev, 8);
    const float g64 = __shfl_sync(FULL, cprev, 16);
    const float g96 = __shfl_sync(FULL, cprev, 24);

    // ---- 4 interleaved searches, ALL probes via shuffle crossbar ----
    // q = pos/4; probe cdf[4q + 4*step4] = cprev of lane (q + step4)
    float uu[4] = { uv.x, uv.y, uv.z, uv.w };
    int q[4];

    #pragma unroll
    for (int s = 0; s < 4; s++) {
        const bool l1 = (g64 <= uu[s]);
        q[s] = l1 ? 16 : 0;
        const float v2 = l1 ? g96 : g32;
        if (v2 <= uu[s]) q[s] += 8;
    }
    float pv[4];
    #pragma unroll
    for (int s = 0; s < 4; s++) pv[s] = __shfl_sync(FULL, cprev, q[s] + 4);  // step 16
    #pragma unroll
    for (int s = 0; s < 4; s++) if (pv[s] <= uu[s]) q[s] += 4;
    #pragma unroll
    for (int s = 0; s < 4; s++) pv[s] = __shfl_sync(FULL, cprev, q[s] + 2);  // step 8
    #pragma unroll
    for (int s = 0; s < 4; s++) if (pv[s] <= uu[s]) q[s] += 2;
    #pragma unroll
    for (int s = 0; s < 4; s++) pv[s] = __shfl_sync(FULL, cprev, q[s] + 1);  // step 4
    #pragma unroll
    for (int s = 0; s < 4; s++) if (pv[s] <= uu[s]) q[s] += 1;

    // final 2 levels: owner lane q holds cdf[4q+1..3] in cv.x/cv.y/cv.z
    float a[4], b[4], c[4];
    #pragma unroll
    for (int s = 0; s < 4; s++) a[s] = __shfl_sync(FULL, cv.x, q[s]);
    #pragma unroll
    for (int s = 0; s < 4; s++) b[s] = __shfl_sync(FULL, cv.y, q[s]);
    #pragma unroll
    for (int s = 0; s < 4; s++) c[s] = __shfl_sync(FULL, cv.z, q[s]);

    int pos[4];
    #pragma unroll
    for (int s = 0; s < 4; s++)
        pos[s] = 4 * q[s] + (int)(a[s] <= uu[s]) + (int)(b[s] <= uu[s]) + (int)(c[s] <= uu[s]);

    // ---- single LDS.64 gather per sample + FMA ----
    float2 f[4];
    #pragma unroll
    for (int s = 0; s < 4; s++) f[s] = ft[pos[s]];

    float r[4];
    #pragma unroll
    for (int s = 0; s < 4; s++)
        r[s] = fmaf(f[s].x, uu[s], f[s].y);

    *(float4*)(out + base_c + 4 * lane) = make_float4(r[0], r[1], r[2], r[3]);
}

extern "C" void kernel_launch(void* const* d_in, const int* in_sizes, int n_in,
                              void* d_out, int out_size) {
    const float* deltas  = (const float*)d_in[0];
    const float* density = (const float*)d_in[1];
    const float* bins    = (const float*)d_in[2];
    const float* u       = (const float*)d_in[3];
    float* out = (float*)d_out;

    int R = in_sizes[0] / NC;               // 131072
    pdf_sampler_kernel<<<R / RAYS_PER_CTA, THREADS>>>(deltas, density, bins, u, out);
}

// round 14
// speedup vs baseline: 1.0793x; 1.0006x over previous
#include <cuda_runtime.h>

#define NC 128
#define EPS 1e-5f
#define RAYS_PER_CTA 8          // 8 warps/CTA, one ray per warp
#define THREADS (RAYS_PER_CTA * 32)
#define FULL 0xffffffffu

__global__ __launch_bounds__(THREADS) void pdf_sampler_kernel(
    const float* __restrict__ deltas,
    const float* __restrict__ density,
    const float* __restrict__ bins,
    const float* __restrict__ u,
    float* __restrict__ out)
{
    const int lane = threadIdx.x & 31;
    const int wrp  = threadIdx.x >> 5;
    const int ray  = blockIdx.x * RAYS_PER_CTA + wrp;

    // fit[p] = (slope, intercept): sample = fma(slope, u, intercept)
    __shared__ __align__(16) float2 fit_sh[RAYS_PER_CTA][NC];
    // cfq[q] = (cdf[4q], cdf[4q+1], cdf[4q+2], cdf[4q+3])
    __shared__ __align__(16) float4 cfq_sh[RAYS_PER_CTA][32];

    const size_t base_c = (size_t)ray * NC;

    // ---- coalesced streaming loads ----
    const float4 dv = __ldcs((const float4*)(deltas  + base_c + 4 * lane));
    const float4 rv = __ldcs((const float4*)(density + base_c + 4 * lane));
    const float4 uv = __ldcs((const float4*)(u       + base_c + 4 * lane));
    const float nearv = __ldg(bins + (size_t)ray * (NC + 1));   // warp-uniform

    // ---- per-lane serial prefixes ----
    const float dd0 = dv.x * rv.x;
    const float dd1 = dv.y * rv.y;
    const float dd2 = dv.z * rv.z;
    const float dd3 = dv.w * rv.w;
    const float pA0 = dd0, pA1 = pA0 + dd1, pA2 = pA1 + dd2, pA3 = pA2 + dd3;
    const float pD0 = dv.x, pD1 = pD0 + dv.y, pD2 = pD1 + dv.z, pD3 = pD2 + dv.w;

    // ---- fused dual warp scan over lane totals ----
    float sA = pA3, sD = pD3;
    #pragma unroll
    for (int o = 1; o < 32; o <<= 1) {
        const float nA = __shfl_up_sync(FULL, sA, o);
        const float nD = __shfl_up_sync(FULL, sD, o);
        if (lane >= o) { sA += nA; sD += nD; }
    }
    const float offA = sA - pA3;
    const float offD = sD - pD3;

    // ---- telescoped cdf: cumsum(w)[i] = 1 - exp(-cumsum(dd)[i]) ----
    const float total = __shfl_sync(FULL, sA, 31);
    const float wsum  = 1.0f - __expf(-total);
    const float pad   = fmaxf(EPS - wsum, 0.0f);
    const float inv   = __fdividef(1.0f, wsum + pad);
    const float ps    = pad * (1.0f / (float)NC);

    const int e = 4 * lane;
    float4 cv;
    cv.x = fminf(1.0f, (1.0f - __expf(-(offA + pA0)) + ps * (float)(e + 1)) * inv);
    cv.y = fminf(1.0f, (1.0f - __expf(-(offA + pA1)) + ps * (float)(e + 2)) * inv);
    cv.z = fminf(1.0f, (1.0f - __expf(-(offA + pA2)) + ps * (float)(e + 3)) * inv);
    cv.w = fminf(1.0f, (1.0f - __expf(-(offA + pA3)) + ps * (float)(e + 4)) * inv);

    const float cprev_raw = __shfl_up_sync(FULL, cv.w, 1);
    const float cprev = (lane == 0) ? 0.0f : cprev_raw;   // cdf[4*lane]

    // ---- per-quad cdf table (1 STS.128) ----
    cfq_sh[wrp][lane] = make_float4(cprev, cv.x, cv.y, cv.z);

    // ---- linear-fit table: slope = delta/clamp(den), intercept = b0 - slope*c0 ----
    const float be0 = nearv + offD;              // bins[e]
    float den0 = cv.x - cprev; den0 = (den0 < EPS) ? 1.0f : den0;
    float den1 = cv.y - cv.x;  den1 = (den1 < EPS) ? 1.0f : den1;
    float den2 = cv.z - cv.y;  den2 = (den2 < EPS) ? 1.0f : den2;
    float den3 = cv.w - cv.z;  den3 = (den3 < EPS) ? 1.0f : den3;
    const float s0 = __fdividef(dv.x, den0);
    const float s1 = __fdividef(dv.y, den1);
    const float s2 = __fdividef(dv.z, den2);
    const float s3 = __fdividef(dv.w, den3);
    const float i0 = fmaf(-s0, cprev, be0);
    const float i1 = fmaf(-s1, cv.x, be0 + pD0);
    const float i2 = fmaf(-s2, cv.y, be0 + pD1);
    const float i3 = fmaf(-s3, cv.z, be0 + pD2);
    *(float4*)(&fit_sh[wrp][e])     = make_float4(s0, i0, s1, i1);
    *(float4*)(&fit_sh[wrp][e + 2]) = make_float4(s2, i2, s3, i3);

    __syncwarp();

    const float2* __restrict__ ft  = fit_sh[wrp];
    const float4* __restrict__ cfq = cfq_sh[wrp];

    // coarse probe values (cdf[32/64/96] = cprev of lanes 8/16/24)
    const float g32 = __shfl_sync(FULL, cprev, 8);
    const float g64 = __shfl_sync(FULL, cprev, 16);
    const float g96 = __shfl_sync(FULL, cprev, 24);

    // ---- 4 interleaved searches: 3 SHFL descent + 1 LDS.128 + 1 LDS.64 ----
    float uu[4] = { uv.x, uv.y, uv.z, uv.w };
    int q[4];

    #pragma unroll
    for (int s = 0; s < 4; s++) {
        const bool l1 = (g64 <= uu[s]);
        q[s] = l1 ? 16 : 0;
        const float v2 = l1 ? g96 : g32;
        if (v2 <= uu[s]) q[s] += 8;
    }
    float pv[4];
    #pragma unroll
    for (int s = 0; s < 4; s++) pv[s] = __shfl_sync(FULL, cprev, q[s] + 4);
    #pragma unroll
    for (int s = 0; s < 4; s++) if (pv[s] <= uu[s]) q[s] += 4;
    #pragma unroll
    for (int s = 0; s < 4; s++) pv[s] = __shfl_sync(FULL, cprev, q[s] + 2);
    #pragma unroll
    for (int s = 0; s < 4; s++) if (pv[s] <= uu[s]) q[s] += 2;
    #pragma unroll
    for (int s = 0; s < 4; s++) pv[s] = __shfl_sync(FULL, cprev, q[s] + 1);
    #pragma unroll
    for (int s = 0; s < 4; s++) if (pv[s] <= uu[s]) q[s] += 1;

    // final 2 levels from one quad gather each
    float4 cq[4];
    #pragma unroll
    for (int s = 0; s < 4; s++) cq[s] = cfq[q[s]];

    int pos[4];
    #pragma unroll
    for (int s = 0; s < 4; s++)
        pos[s] = 4 * q[s] + (int)(cq[s].y <= uu[s]) + (int)(cq[s].z <= uu[s]) + (int)(cq[s].w <= uu[s]);

    // ---- single LDS.64 fit gather per sample + FMA ----
    float2 f[4];
    #pragma unroll
    for (int s = 0; s < 4; s++) f[s] = ft[pos[s]];

    float r[4];
    #pragma unroll
    for (int s = 0; s < 4; s++)
        r[s] = fmaf(f[s].x, uu[s], f[s].y);

    __stcs((float4*)(out + base_c + 4 * lane), make_float4(r[0], r[1], r[2], r[3]));
}

extern "C" void kernel_launch(void* const* d_in, const int* in_sizes, int n_in,
                              void* d_out, int out_size) {
    const float* deltas  = (const float*)d_in[0];
    const float* density = (const float*)d_in[1];
    const float* bins    = (const float*)d_in[2];
    const float* u       = (const float*)d_in[3];
    float* out = (float*)d_out;

    int R = in_sizes[0] / NC;               // 131072
    pdf_sampler_kernel<<<R / RAYS_PER_CTA, THREADS>>>(deltas, density, bins, u, out);
}